// round 5
// baseline (speedup 1.0000x reference)
#include <cuda_runtime.h>
#include <math.h>

#define OUT_DIM 4096
#define DPC     16
#define NCOLS   (OUT_DIM * DPC)   // 65536
#define BATCH   512
#define WPB     256               // windows (output chunks) per block

// Per-column boost factors, batch-invariant: computed once per launch.
__device__ float g_bf[NCOLS];

__global__ void bf_kernel(const float* __restrict__ duty_cycle,
                          const float* __restrict__ boost_strength) {
    int k = blockIdx.x * blockDim.x + threadIdx.x;
    const float td = (float)OUT_DIM / (float)NCOLS;  // 0.0625
    float bs = boost_strength[0];
    g_bf[k] = expf((td - duty_cycle[k]) * bs);
#if __CUDA_ARCH__ >= 900
    cudaTriggerProgrammaticLaunchCompletion();
#endif
}

__global__ void __launch_bounds__(256)
dkw_kernel(const float* __restrict__ x, float* __restrict__ out) {
    __shared__ float prod[4096];          // boosted window span (over-staged to 4096)
    __shared__ int   s_bj[WPB];

    const int tid = threadIdx.x;
    const int b = blockIdx.x >> 4;        // batch row
    const int w = blockIdx.x & 15;        // window-block within row

    const size_t rowoff = (size_t)b * NCOLS;
    const int W0 = 3840 * w;              // window span start (16B aligned)
    const int O0 = 4096 * w;              // output chunk span start
    // In-bounds proof for the 4096-float over-fetch: W0+4096 <= 3840*15+4096 = 61696 < 65536.

    const float4* xw4 = reinterpret_cast<const float4*>(x + rowoff + W0);
    const float4* xc4 = reinterpret_cast<const float4*>(x + rowoff + O0);
    const float4* bf4 = reinterpret_cast<const float4*>(g_bf + W0);

    // ---- Front-load ALL global reads (max MLP; xc held in regs across barriers) ----
    float4 xw[4], xc[4], bv[4];
#pragma unroll
    for (int k = 0; k < 4; ++k) xw[k] = xw4[tid + WPB * k];
#pragma unroll
    for (int k = 0; k < 4; ++k) xc[k] = xc4[tid + WPB * k];

#if __CUDA_ARCH__ >= 900
    cudaGridDependencySynchronize();      // g_bf ready (PDL)
#endif
#pragma unroll
    for (int k = 0; k < 4; ++k) bv[k] = bf4[tid + WPB * k];

    float4* p4 = reinterpret_cast<float4*>(prod);
#pragma unroll
    for (int k = 0; k < 4; ++k) {
        float4 p;
        p.x = xw[k].x * bv[k].x;
        p.y = xw[k].y * bv[k].y;
        p.z = xw[k].z * bv[k].z;
        p.w = xw[k].w * bv[k].w;
        p4[tid + WPB * k] = p;
    }
    __syncthreads();

    // ---- Argmax over window [15*tid, 15*tid+16): stride-15 LDS, conflict-free ----
    const int wb = 15 * tid;
    float best = -INFINITY;
    int bj = 0;
#pragma unroll
    for (int j = 0; j < DPC; ++j) {
        float v = prod[wb + j];
        if (v > best) { best = v; bj = j; }
    }
    s_bj[tid] = bj;
    __syncthreads();

    // ---- Masked store from registers: fully coalesced STG.128 ----
    float4* o4 = reinterpret_cast<float4*>(out + rowoff + O0);
#pragma unroll
    for (int k = 0; k < 4; ++k) {
        int f  = tid + WPB * k;           // float4 index 0..1023
        int c  = f >> 2;                  // window index within block
        int j0 = (f & 3) << 2;            // first j covered by this float4
        int bjc = s_bj[c];
        float4 v;
        v.x = (bjc == j0 + 0) ? xc[k].x : 0.0f;
        v.y = (bjc == j0 + 1) ? xc[k].y : 0.0f;
        v.z = (bjc == j0 + 2) ? xc[k].z : 0.0f;
        v.w = (bjc == j0 + 3) ? xc[k].w : 0.0f;
        o4[f] = v;
    }
}

extern "C" void kernel_launch(void* const* d_in, const int* in_sizes, int n_in,
                              void* d_out, int out_size) {
    const float* x  = (const float*)d_in[0];
    const float* dc = (const float*)d_in[1];
    const float* bs = (const float*)d_in[2];
    float* out = (float*)d_out;

    bf_kernel<<<NCOLS / 256, 256>>>(dc, bs);

    // dkw with Programmatic Dependent Launch: overlaps its x-prefetch with
    // bf_kernel tail + launch latency; correctness guarded by the in-kernel wait.
    cudaLaunchConfig_t cfg = {};
    cfg.gridDim  = dim3(BATCH * (OUT_DIM / WPB), 1, 1);
    cfg.blockDim = dim3(WPB, 1, 1);
    cfg.dynamicSmemBytes = 0;
    cfg.stream = 0;
    cudaLaunchAttribute attr[1];
    attr[0].id = cudaLaunchAttributeProgrammaticStreamSerialization;
    attr[0].val.programmaticStreamSerializationAllowed = 1;
    cfg.attrs = attr;
    cfg.numAttrs = 1;
    cudaLaunchKernelEx(&cfg, dkw_kernel, x, out);
}